// round 1
// baseline (speedup 1.0000x reference)
#include <cuda_runtime.h>

#define RESP 32
#define RESF 64
#define NP   8192
#define NF   65536
#define CH   128
#define EPSV 1e-5f
#define TM   64

// ---- scratch (device globals: allocation-free rule) ----
__device__ int   g_pg[RESP*RESP*RESP];      // parent grid: coord -> parent idx or -1
__device__ float g_h1[NP*CH];               // silu(gn1(feats))
__device__ float g_M1[64*CH*CH];            // aggregated conv1 kernels M1[off][ebit]
__device__ float g_out1[NF*CH];             // conv1 output (pre-GN2)
__device__ float g_h2[NF*CH];               // silu(gn2(out1))
__device__ float g_sum[32];
__device__ float g_sq[32];

// ---------------- grid build ----------------
__global__ void k_init_pg() {
    int i = blockIdx.x * blockDim.x + threadIdx.x;
    if (i < RESP*RESP*RESP) g_pg[i] = -1;
}

__global__ void k_scatter(const int* __restrict__ coords) {
    int i = blockIdx.x * blockDim.x + threadIdx.x;
    if (i < NP) {
        int c0 = coords[i*3+0], c1 = coords[i*3+1], c2 = coords[i*3+2];
        g_pg[(c0*RESP + c1)*RESP + c2] = i;
    }
}

// ---------------- group norm stats ----------------
// one block per group (32 groups, 4 channels each); stats over all rows
template<bool SECOND>
__global__ void k_stats(const float* __restrict__ xin, int nrows) {
    const float* x = SECOND ? g_out1 : xin;
    int g = blockIdx.x;
    float s = 0.f, q = 0.f;
    for (int r = threadIdx.x; r < nrows; r += blockDim.x) {
        float4 v = *reinterpret_cast<const float4*>(x + r*CH + g*4);
        s += (v.x + v.y) + (v.z + v.w);
        q += (v.x*v.x + v.y*v.y) + (v.z*v.z + v.w*v.w);
    }
    __shared__ float ss[256], sq[256];
    ss[threadIdx.x] = s; sq[threadIdx.x] = q;
    __syncthreads();
    for (int st = 128; st > 0; st >>= 1) {
        if (threadIdx.x < st) {
            ss[threadIdx.x] += ss[threadIdx.x + st];
            sq[threadIdx.x] += sq[threadIdx.x + st];
        }
        __syncthreads();
    }
    if (threadIdx.x == 0) { g_sum[g] = ss[0]; g_sq[g] = sq[0]; }
}

// ---------------- normalize + silu ----------------
// processes float4 lanes; each float4 = exactly one group's 4 channels
template<bool SECOND>
__global__ void k_gnsilu(const float* __restrict__ xin,
                         const float* __restrict__ gamma,
                         const float* __restrict__ beta,
                         float invcnt, int n4) {
    int idx = blockIdx.x * blockDim.x + threadIdx.x;
    if (idx >= n4) return;
    const float* x = SECOND ? g_out1 : xin;
    float* outp    = SECOND ? g_h2   : g_h1;
    int g = idx & 31;
    float mean = g_sum[g] * invcnt;
    float var  = g_sq[g] * invcnt - mean * mean;
    float inv  = rsqrtf(var + EPSV);
    float4 v  = reinterpret_cast<const float4*>(x)[idx];
    float4 ga = reinterpret_cast<const float4*>(gamma)[g];
    float4 be = reinterpret_cast<const float4*>(beta)[g];
    float4 o;
    float y;
    y = (v.x - mean) * inv * ga.x + be.x; o.x = y / (1.f + expf(-y));
    y = (v.y - mean) * inv * ga.y + be.y; o.y = y / (1.f + expf(-y));
    y = (v.z - mean) * inv * ga.z + be.z; o.z = y / (1.f + expf(-y));
    y = (v.w - mean) * inv * ga.w + be.w; o.w = y / (1.f + expf(-y));
    reinterpret_cast<float4*>(outp)[idx] = o;
}

// ---------------- build aggregated conv1 kernels ----------------
// M1[off(k)][ebit(j)][c][cc] = sum of W1[d] over d's mapping to that parent-offset
__global__ void k_buildM1(const float* __restrict__ W1) {
    int idx = blockIdx.x * blockDim.x + threadIdx.x;   // < 64*128*128
    if (idx >= 64*CH*CH) return;
    int cc = idx & (CH*CH - 1);
    int m  = idx >> 14;
    int k = m >> 3, j = m & 7;
    int s[3], n[3];
#pragma unroll
    for (int a = 0; a < 3; a++) {
        int o  = (k >> (2 - a)) & 1;
        int eb = (j >> (2 - a)) & 1;
        n[a] = 1 + (o ^ eb);          // 1 or 2 d's merged
        s[a] = -1 + eb * (1 + o);     // starting d
    }
    float acc = 0.f;
    for (int d0 = 0; d0 < n[0]; d0++)
        for (int d1 = 0; d1 < n[1]; d1++)
            for (int d2 = 0; d2 < n[2]; d2++) {
                int k27 = ((s[0]+d0+1)*3 + (s[1]+d1+1))*3 + (s[2]+d2+1);
                acc += W1[k27*CH*CH + cc];
            }
    g_M1[idx] = acc;
}

// ---------------- shared GEMM helpers ----------------
__device__ __forceinline__ void load_AB(const float* __restrict__ hsrc, int src,
                                        const float* __restrict__ Bsrc, int kk,
                                        float (*As)[36], float (*Bs)[CH], int tid) {
    int lr = tid >> 2, lc = (tid & 3) * 8;
    float4 v0 = make_float4(0.f,0.f,0.f,0.f), v1 = v0;
    if (src >= 0) {
        const float4* ap = reinterpret_cast<const float4*>(hsrc + src*CH + kk + lc);
        v0 = ap[0]; v1 = ap[1];
    }
    *reinterpret_cast<float4*>(&As[lr][lc])     = v0;
    *reinterpret_cast<float4*>(&As[lr][lc + 4]) = v1;
    int bc = tid >> 3, bj = (tid & 7) * 16;
    const float4* bp = reinterpret_cast<const float4*>(Bsrc + (kk + bc)*CH + bj);
    float4 w0 = bp[0], w1 = bp[1], w2 = bp[2], w3 = bp[3];
    *reinterpret_cast<float4*>(&Bs[bc][bj +  0]) = w0;
    *reinterpret_cast<float4*>(&Bs[bc][bj +  4]) = w1;
    *reinterpret_cast<float4*>(&Bs[bc][bj +  8]) = w2;
    *reinterpret_cast<float4*>(&Bs[bc][bj + 12]) = w3;
}

__device__ __forceinline__ void mm_tile(const float (*As)[36], const float (*Bs)[CH],
                                        float (*acc)[8], int ty, int tx) {
#pragma unroll
    for (int kc = 0; kc < 32; kc++) {
        float a[4];
#pragma unroll
        for (int i = 0; i < 4; i++) a[i] = As[ty*4 + i][kc];
        float4 u = *reinterpret_cast<const float4*>(&Bs[kc][tx*8]);
        float4 w = *reinterpret_cast<const float4*>(&Bs[kc][tx*8 + 4]);
#pragma unroll
        for (int i = 0; i < 4; i++) {
            acc[i][0] += a[i]*u.x; acc[i][1] += a[i]*u.y;
            acc[i][2] += a[i]*u.z; acc[i][3] += a[i]*u.w;
            acc[i][4] += a[i]*w.x; acc[i][5] += a[i]*w.y;
            acc[i][6] += a[i]*w.z; acc[i][7] += a[i]*w.w;
        }
    }
}

// ---------------- conv1: parent-level, aggregated kernels ----------------
// grid (128 parent-tiles, 8 child offsets), 256 threads
__global__ __launch_bounds__(256)
void k_conv1(const int* __restrict__ coords, const float* __restrict__ b1) {
    __shared__ float As[TM][36];
    __shared__ float Bs[32][CH];
    __shared__ int   s_nb[8][TM];
    __shared__ int   s_pc[TM][3];
    int tid = threadIdx.x;
    int bx = blockIdx.x;
    int ko = blockIdx.y;           // child offset 0..7
    if (tid < TM) {
        int p = bx*TM + tid;
        s_pc[tid][0] = coords[p*3+0];
        s_pc[tid][1] = coords[p*3+1];
        s_pc[tid][2] = coords[p*3+2];
    }
    __syncthreads();
    int o0 = (ko >> 2) & 1, o1 = (ko >> 1) & 1, o2 = ko & 1;
    for (int t = tid; t < 8*TM; t += 256) {
        int j = t >> 6, r = t & 63;
        int q0 = s_pc[r][0] + o0 - 1 + ((j >> 2) & 1);
        int q1 = s_pc[r][1] + o1 - 1 + ((j >> 1) & 1);
        int q2 = s_pc[r][2] + o2 - 1 + (j & 1);
        int nb = -1;
        if ((unsigned)q0 < RESP && (unsigned)q1 < RESP && (unsigned)q2 < RESP)
            nb = g_pg[(q0*RESP + q1)*RESP + q2];
        s_nb[j][r] = nb;
    }
    __syncthreads();

    int ty = tid >> 4, tx = tid & 15;
    float acc[4][8];
#pragma unroll
    for (int i = 0; i < 4; i++)
#pragma unroll
        for (int jj = 0; jj < 8; jj++) acc[i][jj] = 0.f;

    int lr = tid >> 2;
    for (int j = 0; j < 8; j++) {
        const float* Bsrc = g_M1 + (ko*8 + j)*CH*CH;
        int src = s_nb[j][lr];
        for (int kk = 0; kk < CH; kk += 32) {
            load_AB(g_h1, src, Bsrc, kk, As, Bs, tid);
            __syncthreads();
            mm_tile(As, Bs, acc, ty, tx);
            __syncthreads();
        }
    }

    float4 bb0 = *reinterpret_cast<const float4*>(b1 + tx*8);
    float4 bb1 = *reinterpret_cast<const float4*>(b1 + tx*8 + 4);
#pragma unroll
    for (int i = 0; i < 4; i++) {
        int r = ty*4 + i;
        int orow = (bx*TM + r)*8 + ko;
        float4 u = make_float4(acc[i][0]+bb0.x, acc[i][1]+bb0.y, acc[i][2]+bb0.z, acc[i][3]+bb0.w);
        float4 w = make_float4(acc[i][4]+bb1.x, acc[i][5]+bb1.y, acc[i][6]+bb1.z, acc[i][7]+bb1.w);
        *reinterpret_cast<float4*>(g_out1 + orow*CH + tx*8)     = u;
        *reinterpret_cast<float4*>(g_out1 + orow*CH + tx*8 + 4) = w;
    }
}

// ---------------- conv2: fine-level 27-tap + bias + residual ----------------
// grid: 1024 tiles of 64 fine rows, 256 threads
__global__ __launch_bounds__(256)
void k_conv2(const int* __restrict__ coords, const float* __restrict__ W2,
             const float* __restrict__ b2, const float* __restrict__ feats,
             float* __restrict__ out) {
    __shared__ float As[TM][36];
    __shared__ float Bs[32][CH];
    __shared__ int   s_f[TM][3];
    __shared__ int   s_nb[TM];
    int tid = threadIdx.x;
    int bx = blockIdx.x;
    if (tid < TM) {
        int row = bx*TM + tid;
        int pi = row >> 3, k8 = row & 7;
        s_f[tid][0] = 2*coords[pi*3+0] + ((k8 >> 2) & 1);
        s_f[tid][1] = 2*coords[pi*3+1] + ((k8 >> 1) & 1);
        s_f[tid][2] = 2*coords[pi*3+2] + (k8 & 1);
    }
    __syncthreads();

    int ty = tid >> 4, tx = tid & 15;
    float acc[4][8];
#pragma unroll
    for (int i = 0; i < 4; i++)
#pragma unroll
        for (int jj = 0; jj < 8; jj++) acc[i][jj] = 0.f;

    int lr = tid >> 2;
    for (int k = 0; k < 27; k++) {
        int d0 = k/9 - 1, d1 = (k/3)%3 - 1, d2 = k%3 - 1;
        if (tid < TM) {
            int f0 = s_f[tid][0] + d0;
            int f1 = s_f[tid][1] + d1;
            int f2 = s_f[tid][2] + d2;
            int nb = -1;
            if ((unsigned)f0 < RESF && (unsigned)f1 < RESF && (unsigned)f2 < RESF) {
                int p = g_pg[((f0 >> 1)*RESP + (f1 >> 1))*RESP + (f2 >> 1)];
                if (p >= 0) nb = p*8 + (((f0 & 1) << 2) | ((f1 & 1) << 1) | (f2 & 1));
            }
            s_nb[tid] = nb;
        }
        __syncthreads();
        int src = s_nb[lr];
        const float* Bsrc = W2 + k*CH*CH;
        for (int kk = 0; kk < CH; kk += 32) {
            load_AB(g_h2, src, Bsrc, kk, As, Bs, tid);
            __syncthreads();
            mm_tile(As, Bs, acc, ty, tx);
            __syncthreads();
        }
    }

    float4 bb0 = *reinterpret_cast<const float4*>(b2 + tx*8);
    float4 bb1 = *reinterpret_cast<const float4*>(b2 + tx*8 + 4);
#pragma unroll
    for (int i = 0; i < 4; i++) {
        int r = ty*4 + i;
        int row = bx*TM + r;
        int parent = row >> 3;
        float4 x0 = *reinterpret_cast<const float4*>(feats + parent*CH + tx*8);
        float4 x1 = *reinterpret_cast<const float4*>(feats + parent*CH + tx*8 + 4);
        float4 u = make_float4(acc[i][0]+bb0.x+x0.x, acc[i][1]+bb0.y+x0.y,
                               acc[i][2]+bb0.z+x0.z, acc[i][3]+bb0.w+x0.w);
        float4 w = make_float4(acc[i][4]+bb1.x+x1.x, acc[i][5]+bb1.y+x1.y,
                               acc[i][6]+bb1.z+x1.z, acc[i][7]+bb1.w+x1.w);
        *reinterpret_cast<float4*>(out + row*CH + tx*8)     = u;
        *reinterpret_cast<float4*>(out + row*CH + tx*8 + 4) = w;
    }
}

// ---------------- launch ----------------
extern "C" void kernel_launch(void* const* d_in, const int* in_sizes, int n_in,
                              void* d_out, int out_size) {
    const float* feats  = (const float*)d_in[0];
    const float* gamma1 = (const float*)d_in[1];
    const float* beta1  = (const float*)d_in[2];
    const float* W1     = (const float*)d_in[3];
    const float* b1     = (const float*)d_in[4];
    const float* gamma2 = (const float*)d_in[5];
    const float* beta2  = (const float*)d_in[6];
    const float* W2     = (const float*)d_in[7];
    const float* b2     = (const float*)d_in[8];
    const int*   coords = (const int*)d_in[9];
    float* out = (float*)d_out;

    k_init_pg<<<(RESP*RESP*RESP + 255)/256, 256>>>();
    k_scatter<<<(NP + 255)/256, 256>>>(coords);

    // GN1 + SiLU -> g_h1
    k_stats<false><<<32, 256>>>(feats, NP);
    k_gnsilu<false><<<(NP*32 + 255)/256, 256>>>(feats, gamma1, beta1, 1.f/(NP*4), NP*32);

    // aggregated conv1 kernels
    k_buildM1<<<(64*CH*CH + 255)/256, 256>>>(W1);

    // conv1 (parent-level) -> g_out1
    dim3 g1(NP/TM, 8);
    k_conv1<<<g1, 256>>>(coords, b1);

    // GN2 + SiLU -> g_h2
    k_stats<true><<<32, 256>>>(nullptr, NF);
    k_gnsilu<true><<<(NF*32 + 255)/256, 256>>>(nullptr, gamma2, beta2, 1.f/(NF*4), NF*32);

    // conv2 (fine-level) + bias + residual -> out
    k_conv2<<<NF/TM, 256>>>(coords, W2, b2, feats, out);
}

// round 3
// speedup vs baseline: 4.9278x; 4.9278x over previous
#include <cuda_runtime.h>
#include <cstdint>

#define RESP 32
#define RESF 64
#define NP   8192
#define NF   65536
#define CH   128
#define EPSV 1e-5f

// ---- scratch (device globals: allocation-free rule) ----
__device__ int   g_pg[RESP*RESP*RESP];
__device__ float g_h1[NP*CH];
__device__ float g_out1[NF*CH];
__device__ float g_h2[NF*CH];
__device__ float g_M1s[64*CH*CH];   // aggregated conv1 weights, [mat][n][k], tf32-rounded
__device__ float g_W2s[27*CH*CH];   // conv2 weights, [mat][n][k], tf32-rounded
__device__ float g_sum[32], g_sq[32];
__device__ float g_ps[32][32], g_pq[32][32];

// ================= helpers =================
__device__ __forceinline__ uint32_t smem_u32(const void* p) {
    uint32_t a;
    asm("{ .reg .u64 t; cvta.to.shared.u64 t, %1; cvt.u32.u64 %0, t; }" : "=r"(a) : "l"(p));
    return a;
}
__device__ __forceinline__ float tf32r(float x) {
    uint32_t u;
    asm("cvt.rna.tf32.f32 %0, %1;" : "=r"(u) : "f"(x));
    return __uint_as_float(u);
}
__device__ __forceinline__ void cp16(uint32_t dst, const void* src, uint32_t ssz) {
    asm volatile("cp.async.cg.shared.global [%0], [%1], 16, %2;" :: "r"(dst), "l"(src), "r"(ssz));
}
__device__ __forceinline__ void cp_commit() { asm volatile("cp.async.commit_group;"); }
#define CP_WAIT(n) asm volatile("cp.async.wait_group %0;" :: "n"(n) : "memory")

__device__ __forceinline__ void ldsm4(uint32_t* r, uint32_t addr) {
    asm volatile("ldmatrix.sync.aligned.m8n8.x4.shared.b16 {%0,%1,%2,%3}, [%4];"
        : "=r"(r[0]), "=r"(r[1]), "=r"(r[2]), "=r"(r[3]) : "r"(addr));
}
__device__ __forceinline__ void mma_tf32(float* d, const uint32_t* a, const uint32_t* b) {
    asm volatile("mma.sync.aligned.m16n8k8.row.col.f32.tf32.tf32.f32 "
        "{%0,%1,%2,%3}, {%4,%5,%6,%7}, {%8,%9}, {%0,%1,%2,%3};"
        : "+f"(d[0]), "+f"(d[1]), "+f"(d[2]), "+f"(d[3])
        : "r"(a[0]), "r"(a[1]), "r"(a[2]), "r"(a[3]), "r"(b[0]), "r"(b[1]));
}

// ================= grid build =================
__global__ void k_init_pg() {
    int i = blockIdx.x * blockDim.x + threadIdx.x;
    if (i < RESP*RESP*RESP) g_pg[i] = -1;
}
__global__ void k_scatter(const int* __restrict__ coords) {
    int i = blockIdx.x * blockDim.x + threadIdx.x;
    if (i < NP) g_pg[(coords[i*3]*RESP + coords[i*3+1])*RESP + coords[i*3+2]] = i;
}

// ================= group norm =================
template<bool SECOND>
__global__ void k_stats1(const float* __restrict__ xin, int nrows, int nsl) {
    const float* x = SECOND ? g_out1 : xin;
    int g = blockIdx.x, sl = blockIdx.y;
    int per = nrows / nsl, r0 = sl * per;
    float s = 0.f, q = 0.f;
    for (int r = r0 + threadIdx.x; r < r0 + per; r += blockDim.x) {
        float4 v = *reinterpret_cast<const float4*>(x + r*CH + g*4);
        s += (v.x + v.y) + (v.z + v.w);
        q += (v.x*v.x + v.y*v.y) + (v.z*v.z + v.w*v.w);
    }
    __shared__ float ss[256], sq[256];
    ss[threadIdx.x] = s; sq[threadIdx.x] = q;
    __syncthreads();
    for (int st = 128; st > 0; st >>= 1) {
        if (threadIdx.x < st) { ss[threadIdx.x] += ss[threadIdx.x+st]; sq[threadIdx.x] += sq[threadIdx.x+st]; }
        __syncthreads();
    }
    if (threadIdx.x == 0) { g_ps[g][sl] = ss[0]; g_pq[g][sl] = sq[0]; }
}
__global__ void k_stats2(int nsl) {
    int g = blockIdx.x, t = threadIdx.x;
    float s = (t < nsl) ? g_ps[g][t] : 0.f;
    float q = (t < nsl) ? g_pq[g][t] : 0.f;
#pragma unroll
    for (int o = 16; o > 0; o >>= 1) {
        s += __shfl_xor_sync(0xffffffff, s, o);
        q += __shfl_xor_sync(0xffffffff, q, o);
    }
    if (t == 0) { g_sum[g] = s; g_sq[g] = q; }
}
template<bool SECOND>
__global__ void k_gnsilu(const float* __restrict__ xin,
                         const float* __restrict__ gamma, const float* __restrict__ beta,
                         float invcnt, int n4) {
    int idx = blockIdx.x * blockDim.x + threadIdx.x;
    if (idx >= n4) return;
    const float* x = SECOND ? g_out1 : xin;
    float* outp    = SECOND ? g_h2   : g_h1;
    int g = idx & 31;
    float mean = g_sum[g] * invcnt;
    float var  = g_sq[g] * invcnt - mean * mean;
    float inv  = rsqrtf(var + EPSV);
    float4 v  = reinterpret_cast<const float4*>(x)[idx];
    float4 ga = reinterpret_cast<const float4*>(gamma)[g];
    float4 be = reinterpret_cast<const float4*>(beta)[g];
    float4 o; float y;
    y = (v.x - mean)*inv*ga.x + be.x; o.x = tf32r(y / (1.f + expf(-y)));
    y = (v.y - mean)*inv*ga.y + be.y; o.y = tf32r(y / (1.f + expf(-y)));
    y = (v.z - mean)*inv*ga.z + be.z; o.z = tf32r(y / (1.f + expf(-y)));
    y = (v.w - mean)*inv*ga.w + be.w; o.w = tf32r(y / (1.f + expf(-y)));
    reinterpret_cast<float4*>(outp)[idx] = o;
}

// ================= weight preprocessing: transpose to [mat][n][k] + tf32 round =================
__global__ void k_buildM1s(const float* __restrict__ W1) {
    int idx = blockIdx.x * blockDim.x + threadIdx.x;
    if (idx >= 64*CH*CH) return;
    int m = idx >> 14, rest = idx & 16383;
    int n = rest >> 7, kk = rest & 127;
    int k = m >> 3, j = m & 7;
    int s[3], cnt[3];
#pragma unroll
    for (int a = 0; a < 3; a++) {
        int o  = (k >> (2 - a)) & 1;
        int eb = (j >> (2 - a)) & 1;
        cnt[a] = 1 + (o ^ eb);
        s[a]   = -1 + eb * (1 + o);
    }
    float acc = 0.f;
    for (int d0 = 0; d0 < cnt[0]; d0++)
        for (int d1 = 0; d1 < cnt[1]; d1++)
            for (int d2 = 0; d2 < cnt[2]; d2++) {
                int k27 = ((s[0]+d0+1)*3 + (s[1]+d1+1))*3 + (s[2]+d2+1);
                acc += W1[k27*CH*CH + kk*CH + n];
            }
    g_M1s[idx] = tf32r(acc);
}
__global__ void k_buildW2s(const float* __restrict__ W2) {
    int idx = blockIdx.x * blockDim.x + threadIdx.x;
    if (idx >= 27*CH*CH) return;
    int m = idx >> 14, rest = idx & 16383;
    int n = rest >> 7, kk = rest & 127;
    g_W2s[idx] = tf32r(W2[m*CH*CH + kk*CH + n]);
}

// ================= tf32 mma conv kernels =================
// CTA: 128 rows x 128 cols, 8 warps (4m x 2n), warp tile 32x64.
// 3-stage cp.async pipeline, BK=16, row pitch 20 floats (conflict-free ldmatrix).
#define STG_PITCH 10240          // 128 rows * 80 B
#define ROW_P 80

template<int NTAPS, bool ISC2>
__global__ __launch_bounds__(256)
void k_convmma(const int* __restrict__ coords, const float* __restrict__ bias,
               const float* __restrict__ feats, float* __restrict__ dout) {
    extern __shared__ char dsm[];
    uint32_t smA = smem_u32(dsm);              // 3 * 10240
    uint32_t smB = smA + 3*STG_PITCH;          // 3 * 10240
    int* snb = (int*)(dsm + 6*STG_PITCH);      // NTAPS*128 ints

    const float* hsrc = ISC2 ? g_h2  : g_h1;
    const float* Wp   = ISC2 ? g_W2s : g_M1s;
    float* outp       = ISC2 ? dout  : g_out1;

    int tid = threadIdx.x, lane = tid & 31, wid = tid >> 5;
    int wm = wid & 3, wn = wid >> 2;
    int bx = blockIdx.x, ko = blockIdx.y;
    const int matBase = ISC2 ? 0 : ko*8;

    // ---- neighbor precompute ----
    for (int t = tid; t < NTAPS*128; t += 256) {
        int tap = t >> 7, row = t & 127;
        int nb = -1;
        if (ISC2) {
            int grow = bx*128 + row;
            int pi = grow >> 3, k8 = grow & 7;
            int f0 = 2*coords[pi*3+0] + ((k8 >> 2) & 1) + (tap/9 - 1);
            int f1 = 2*coords[pi*3+1] + ((k8 >> 1) & 1) + ((tap/3) % 3 - 1);
            int f2 = 2*coords[pi*3+2] + (k8 & 1)        + (tap % 3 - 1);
            if ((unsigned)f0 < RESF && (unsigned)f1 < RESF && (unsigned)f2 < RESF) {
                int p = g_pg[((f0 >> 1)*RESP + (f1 >> 1))*RESP + (f2 >> 1)];
                if (p >= 0) nb = p*8 + (((f0 & 1) << 2) | ((f1 & 1) << 1) | (f2 & 1));
            }
        } else {
            int p = bx*128 + row;
            int q0 = coords[p*3+0] + ((ko >> 2) & 1) - 1 + ((tap >> 2) & 1);
            int q1 = coords[p*3+1] + ((ko >> 1) & 1) - 1 + ((tap >> 1) & 1);
            int q2 = coords[p*3+2] + (ko & 1)        - 1 + (tap & 1);
            if ((unsigned)q0 < RESP && (unsigned)q1 < RESP && (unsigned)q2 < RESP)
                nb = g_pg[(q0*RESP + q1)*RESP + q2];
        }
        snb[t] = nb;
    }
    __syncthreads();

    // per-thread loader coords: 2 cp16 for A row, 2 for B row
    const int lrow = tid >> 1, lhalf = tid & 1;

    // per-thread ldmatrix bases (stage-0 absolute; add stage offset later)
    // A: x4 matrices = {rows0-7 k0-3, rows8-15 k0-3, rows0-7 k4-7, rows8-15 k4-7}
    uint32_t Abase = smA + (uint32_t)((wm*32 + ((lane>>3)&1)*8 + (lane&7))*ROW_P + ((lane>>4)&1)*16);
    // B: x4 matrices = {nt k0-3, nt k4-7, nt+1 k0-3, nt+1 k4-7}
    uint32_t Bbase = smB + (uint32_t)((wn*64 + ((lane>>4)&1)*8 + (lane&7))*ROW_P + ((lane>>3)&1)*16);

    float acc[2][8][4];
#pragma unroll
    for (int mt = 0; mt < 2; mt++)
#pragma unroll
        for (int nt = 0; nt < 8; nt++)
#pragma unroll
            for (int c = 0; c < 4; c++) acc[mt][nt][c] = 0.f;

    const int T = NTAPS * 8;

    // prologue: stages 0,1
#pragma unroll
    for (int s = 0; s < 2; s++) {
        int tap = s >> 3, c0 = (s & 7) * 16;
        int src = snb[tap*128 + lrow];
        uint32_t ssz = src >= 0 ? 16u : 0u;
        const float* ap = hsrc + (src < 0 ? 0 : src)*CH + c0 + lhalf*8;
        uint32_t ad = smA + s*STG_PITCH + lrow*ROW_P + lhalf*32;
        cp16(ad, ap, ssz); cp16(ad + 16, ap + 4, ssz);
        const float* bp = Wp + ((matBase + tap)*128 + lrow)*128 + c0 + lhalf*8;
        uint32_t bd = smB + s*STG_PITCH + lrow*ROW_P + lhalf*32;
        cp16(bd, bp, 16u); cp16(bd + 16, bp + 4, 16u);
        cp_commit();
    }

    int sbuf = 0;
    for (int s = 0; s < T; s++) {
        if (s + 2 < T) CP_WAIT(1); else CP_WAIT(0);
        __syncthreads();
        if (s + 2 < T) {
            int s2 = s + 2;
            int tap = s2 >> 3, c0 = (s2 & 7) * 16;
            int buf2 = sbuf + 2; if (buf2 >= 3) buf2 -= 3;
            int src = snb[tap*128 + lrow];
            uint32_t ssz = src >= 0 ? 16u : 0u;
            const float* ap = hsrc + (src < 0 ? 0 : src)*CH + c0 + lhalf*8;
            uint32_t ad = smA + buf2*STG_PITCH + lrow*ROW_P + lhalf*32;
            cp16(ad, ap, ssz); cp16(ad + 16, ap + 4, ssz);
            const float* bp = Wp + ((matBase + tap)*128 + lrow)*128 + c0 + lhalf*8;
            uint32_t bd = smB + buf2*STG_PITCH + lrow*ROW_P + lhalf*32;
            cp16(bd, bp, 16u); cp16(bd + 16, bp + 4, 16u);
            cp_commit();
        }
        uint32_t ao = sbuf*STG_PITCH, bo = sbuf*STG_PITCH;
#pragma unroll
        for (int ks = 0; ks < 2; ks++) {
            uint32_t kb = ks * 32;   // 8 floats = 32 bytes
            uint32_t a[2][4];
            ldsm4(a[0], Abase + ao + kb);
            ldsm4(a[1], Abase + ao + kb + 16*ROW_P);
            uint32_t b[4][4];
#pragma unroll
            for (int p = 0; p < 4; p++) ldsm4(b[p], Bbase + bo + kb + p*16*ROW_P);
#pragma unroll
            for (int mt = 0; mt < 2; mt++)
#pragma unroll
                for (int nt = 0; nt < 8; nt++)
                    mma_tf32(acc[mt][nt], a[mt], b[nt >> 1] + (nt & 1)*2);
        }
        sbuf++; if (sbuf == 3) sbuf = 0;
    }

    // ---- epilogue: direct register -> gmem, fused bias (+residual) ----
#pragma unroll
    for (int mt = 0; mt < 2; mt++) {
        int rl = wm*32 + mt*16 + (lane >> 2);
#pragma unroll
        for (int half = 0; half < 2; half++) {
            int row = rl + half*8;
            int orow, prow;
            if (ISC2) { orow = bx*128 + row; prow = orow >> 3; }
            else      { orow = (bx*128 + row)*8 + ko; prow = -1; }
#pragma unroll
            for (int nt = 0; nt < 8; nt++) {
                int col = wn*64 + nt*8 + (lane & 3)*2;
                float2 bb = *reinterpret_cast<const float2*>(bias + col);
                float vx = acc[mt][nt][half*2 + 0] + bb.x;
                float vy = acc[mt][nt][half*2 + 1] + bb.y;
                if (ISC2) {
                    float2 rr = *reinterpret_cast<const float2*>(feats + prow*CH + col);
                    vx += rr.x; vy += rr.y;
                }
                float2 o; o.x = vx; o.y = vy;
                *reinterpret_cast<float2*>(outp + orow*CH + col) = o;
            }
        }
    }
}

// ================= launch =================
extern "C" void kernel_launch(void* const* d_in, const int* in_sizes, int n_in,
                              void* d_out, int out_size) {
    const float* feats  = (const float*)d_in[0];
    const float* gamma1 = (const float*)d_in[1];
    const float* beta1  = (const float*)d_in[2];
    const float* W1     = (const float*)d_in[3];
    const float* b1     = (const float*)d_in[4];
    const float* gamma2 = (const float*)d_in[5];
    const float* beta2  = (const float*)d_in[6];
    const float* W2     = (const float*)d_in[7];
    const float* b2     = (const float*)d_in[8];
    const int*   coords = (const int*)d_in[9];
    float* out = (float*)d_out;

    const int smem1 = 6*STG_PITCH + 8*128*4;    // 65536
    const int smem2 = 6*STG_PITCH + 27*128*4;   // 75264
    cudaFuncSetAttribute(k_convmma<8,false>, cudaFuncAttributeMaxDynamicSharedMemorySize, smem1);
    cudaFuncSetAttribute(k_convmma<27,true>, cudaFuncAttributeMaxDynamicSharedMemorySize, smem2);

    k_init_pg<<<128, 256>>>();
    k_scatter<<<32, 256>>>(coords);
    k_buildM1s<<<4096, 256>>>(W1);
    k_buildW2s<<<1728, 256>>>(W2);

    // GN1 + SiLU -> g_h1 (tf32-rounded)
    k_stats1<false><<<dim3(32, 8), 256>>>(feats, NP, 8);
    k_stats2<<<32, 32>>>(8);
    k_gnsilu<false><<<(NP*32 + 255)/256, 256>>>(feats, gamma1, beta1, 1.f/(NP*4), NP*32);

    // conv1 (parent-level, aggregated taps) -> g_out1
    k_convmma<8,false><<<dim3(64, 8), 256, smem1>>>(coords, b1, nullptr, nullptr);

    // GN2 + SiLU -> g_h2 (tf32-rounded)
    k_stats1<true><<<dim3(32, 32), 256>>>(nullptr, NF, 32);
    k_stats2<<<32, 32>>>(32);
    k_gnsilu<true><<<(NF*32 + 255)/256, 256>>>(nullptr, gamma2, beta2, 1.f/(NF*4), NF*32);

    // conv2 (fine-level, 27 taps) + bias + residual -> out
    k_convmma<27,true><<<512, 256, smem2>>>(coords, b2, feats, out);
}